// round 3
// baseline (speedup 1.0000x reference)
#include <cuda_runtime.h>
#include <cstddef>

#define NB 1024          // 32*32 nodes per time slice
#define NT 9
#define TN (NT * NB)     // 9216
#define RPC 4            // rows per CTA
#define MAXN 137         // max nodes in per-CTA coef window (66+69+pad)

// ---------------------------------------------------------------------------
// Per-node 9-point stencil coefficients of A at time slice ts (= t+1).
// j = (dy+1)*3 + (dx+1); Dirichlet-invalid moves = exact 0.
// ---------------------------------------------------------------------------
__device__ __forceinline__ void coef9(const float* __restrict__ kappa,
                                      const float* __restrict__ m,
                                      const float* __restrict__ H,
                                      int n, int ts, float* c) {
    float kap = kappa[n * NT + ts];
    float k2  = kap * kap;
    float m1  = m[(0 * NB + n) * NT + ts];
    float m2  = m[(1 * NB + n) * NT + ts];
    float H11 = H[(0 * NB + n) * NT + ts];
    float H12 = H[(1 * NB + n) * NT + ts];
    float H22 = H[(3 * NB + n) * NT + ts];

    int ix = n & 31, iy = n >> 5;
    bool xm = ix > 0, xp = ix < 31, ym = iy > 0, yp = iy < 31;

    c[4] = k2 + 2.0f * H11 + 2.0f * H22;
    c[5] = xp         ? ( 0.5f * m1 - H11) : 0.0f;
    c[3] = xm         ? (-0.5f * m1 - H11) : 0.0f;
    c[7] = yp         ? ( 0.5f * m2 - H22) : 0.0f;
    c[1] = ym         ? (-0.5f * m2 - H22) : 0.0f;
    c[8] = (xp && yp) ? (-0.5f * H12)      : 0.0f;
    c[2] = (xp && ym) ? ( 0.5f * H12)      : 0.0f;
    c[6] = (xm && yp) ? ( 0.5f * H12)      : 0.0f;
    c[0] = (xm && ym) ? (-0.5f * H12)      : 0.0f;
}

// ---------------------------------------------------------------------------
// Band-value helpers reading the CTA-local shared coef table (nodes indexed
// relative to `base`; all accessed nodes are guaranteed inside the window).
// ---------------------------------------------------------------------------
__device__ __forceinline__ float offdiag_val(const float* __restrict__ sA,
                                             int base, int p, int q) {
    // -0.5*(invM[p][q] + invM[q][p]),  invM = I + A
    int d = q - p + 33;
    if ((unsigned)d > 66u || (d & 31) > 2) return 0.0f;
    int j = (d >> 5) * 3 + (d & 31);
    float add = (j == 4) ? 1.0f : 0.0f;
    float a = sA[(p - base) * 9 + j] + add;
    float b = sA[(q - base) * 9 + (8 - j)] + add;
    return -0.5f * (a + b);
}

__device__ __forceinline__ float diag_val(const float* __restrict__ sA,
                                          int base, int i, int p, int q) {
    int delta = q - p;
    int ey = ((delta + 66) + 2) / 32 - 2;
    int ex = delta - ey * 32;
    float v;
    if (i == 0) {
        // (A^T A)[p][q] = sum_r A[r][p] * A[r][q]
        float acc = 0.0f;
#pragma unroll
        for (int j = 0; j < 9; j++) {
            int dy = j / 3 - 1, dx = j - (j / 3) * 3 - 1;
            int r = p + dy * 32 + dx;
            if (r < 0 || r >= NB) continue;
            int ddy = ey - dy, ddx = ex - dx;
            if (ddy < -1 || ddy > 1 || ddx < -1 || ddx > 1) continue;
            int j2 = (ddy + 1) * 3 + (ddx + 1);
            acc += sA[(r - base) * 9 + (8 - j)] * sA[(r - base) * 9 + j2];
        }
        v = acc + ((q == p) ? 1.05f : 0.0f);
    } else {
        float mmpq = 0.0f, mmqp = 0.0f;
#pragma unroll
        for (int j = 0; j < 9; j++) {
            int dy = j / 3 - 1, dx = j - (j / 3) * 3 - 1;
            {   // MM[p][q]: p -> r -> q
                int r = p + dy * 32 + dx;
                int ddy = ey - dy, ddx = ex - dx;
                if (r >= 0 && r < NB &&
                    ddy >= -1 && ddy <= 1 && ddx >= -1 && ddx <= 1) {
                    int j2 = (ddy + 1) * 3 + (ddx + 1);
                    float a = sA[(p - base) * 9 + j]  + ((j  == 4) ? 1.0f : 0.0f);
                    float b = sA[(r - base) * 9 + j2] + ((j2 == 4) ? 1.0f : 0.0f);
                    mmpq += a * b;
                }
            }
            {   // MM[q][p]: q -> s -> p
                int s = q + dy * 32 + dx;
                int ddy = -ey - dy, ddx = -ex - dx;
                if (s >= 0 && s < NB &&
                    ddy >= -1 && ddy <= 1 && ddx >= -1 && ddx <= 1) {
                    int j2 = (ddy + 1) * 3 + (ddx + 1);
                    float a = sA[(q - base) * 9 + j]  + ((j  == 4) ? 1.0f : 0.0f);
                    float b = sA[(s - base) * 9 + j2] + ((j2 == 4) ? 1.0f : 0.0f);
                    mmqp += a * b;
                }
            }
        }
        v = 0.5f * (mmpq + mmqp) +
            ((q == p) ? ((i < 8) ? 1.05f : 0.05f) : 0.0f);
    }
    return v;
}

// ---------------------------------------------------------------------------
// Single fused kernel: one CTA per 4 output rows. Prologue builds the <=2
// slice coefficient tables this CTA needs in shared memory; main loop streams
// 9216 floats per row as float4s, every byte written exactly once.
// ---------------------------------------------------------------------------
__global__ __launch_bounds__(256)
void fill_kernel(const float* __restrict__ kappa,
                 const float* __restrict__ m,
                 const float* __restrict__ H,
                 float* __restrict__ out) {
    int r0 = blockIdx.x * RPC;          // first row handled by this CTA
    int i  = r0 >> 10;                  // block row (rows never straddle)
    int p0 = r0 & (NB - 1);

    // coefficient window: all node accesses lie in [p-66, p+33+33] per row
    int base = max(0, p0 - 66);
    int hi   = min(NB, p0 + RPC - 1 + 67);
    int cnt  = hi - base;

    // needed slices: s0 = diag/left slice, s1 = right slice (i in 1..7)
    int s0  = (i == 0) ? 0 : (i - 1);
    int nsl = (i >= 1 && i <= 7) ? 2 : 1;

    __shared__ float sh[2][MAXN * 9];
    for (int idx = threadIdx.x; idx < cnt * nsl; idx += 256) {
        int sl   = (idx >= cnt) ? 1 : 0;
        int loc  = idx - sl * cnt;
        int slice = sl ? i : s0;
        float c[9];
        coef9(kappa, m, H, base + loc, slice + 1, c);
#pragma unroll
        for (int j = 0; j < 9; j++) sh[sl][loc * 9 + j] = c[j];
    }
    __syncthreads();

    const float* sh0 = sh[0];
    const float* shR = (i == 0) ? sh[0] : sh[1];   // right offdiag slice = i
    int q0 = threadIdx.x << 2;                     // column within block

    for (int rr = 0; rr < RPC; rr++) {
        int p = p0 + rr;
        float4* rowp = (float4*)(out + (size_t)(r0 + rr) * TN);

#pragma unroll
        for (int it = 0; it < 9; it++) {           // column block == it
            float4 v = make_float4(0.f, 0.f, 0.f, 0.f);
            if (it == i) {
                if (q0 + 3 >= p - 66 && q0 <= p + 66) {
                    v.x = diag_val(sh0, base, i, p, q0);
                    v.y = diag_val(sh0, base, i, p, q0 + 1);
                    v.z = diag_val(sh0, base, i, p, q0 + 2);
                    v.w = diag_val(sh0, base, i, p, q0 + 3);
                }
            } else if (it + 1 == i) {              // left block, slice i-1
                if (q0 + 3 >= p - 33 && q0 <= p + 33) {
                    v.x = offdiag_val(sh0, base, p, q0);
                    v.y = offdiag_val(sh0, base, p, q0 + 1);
                    v.z = offdiag_val(sh0, base, p, q0 + 2);
                    v.w = offdiag_val(sh0, base, p, q0 + 3);
                }
            } else if (it == i + 1) {              // right block, slice i
                if (q0 + 3 >= p - 33 && q0 <= p + 33) {
                    v.x = offdiag_val(shR, base, p, q0);
                    v.y = offdiag_val(shR, base, p, q0 + 1);
                    v.z = offdiag_val(shR, base, p, q0 + 2);
                    v.w = offdiag_val(shR, base, p, q0 + 3);
                }
            }
            __stcs(rowp + it * 256 + threadIdx.x, v);
        }
    }
}

// ---------------------------------------------------------------------------
// Launcher. Inputs: kappa, m, H, tau (unused). Output: fp32 [1, 9216, 9216].
// ---------------------------------------------------------------------------
extern "C" void kernel_launch(void* const* d_in, const int* in_sizes, int n_in,
                              void* d_out, int out_size) {
    const float* kappa = (const float*)d_in[0];
    const float* m     = (const float*)d_in[1];
    const float* H     = (const float*)d_in[2];
    float* out = (float*)d_out;

    fill_kernel<<<TN / RPC, 256>>>(kappa, m, H, out);
}

// round 4
// speedup vs baseline: 1.1804x; 1.1804x over previous
#include <cuda_runtime.h>
#include <cstddef>

#define NB 1024          // 32*32 nodes per time slice
#define NT 9
#define TN (NT * NB)     // 9216
#define DW 144           // diag scratch row width (133 used, padded)
#define OW 72            // offdiag scratch row width (67 used, padded)

// Precomputed band values.
// g_D[i][p][d+66] = Q[i*NB+p][i*NB+p+d]          (diag blocks, |d|<=66)
// g_O[t][p][d+33] = Q[t*NB+p][(t+1)*NB+p+d]      (offdiag blocks, |d|<=33)
__device__ float g_D[9 * NB * DW];
__device__ float g_O[8 * NB * OW];

// ---------------------------------------------------------------------------
// Per-node 9-point stencil coefficients of A at time slice ts.
// j = (dy+1)*3 + (dx+1); Dirichlet-invalid moves = exact 0.
// ---------------------------------------------------------------------------
__device__ __forceinline__ void coef9(const float* __restrict__ kappa,
                                      const float* __restrict__ m,
                                      const float* __restrict__ H,
                                      int n, int ts, float* c) {
    float kap = kappa[n * NT + ts];
    float k2  = kap * kap;
    float m1  = m[(0 * NB + n) * NT + ts];
    float m2  = m[(1 * NB + n) * NT + ts];
    float H11 = H[(0 * NB + n) * NT + ts];
    float H12 = H[(1 * NB + n) * NT + ts];
    float H22 = H[(3 * NB + n) * NT + ts];

    int ix = n & 31, iy = n >> 5;
    bool xm = ix > 0, xp = ix < 31, ym = iy > 0, yp = iy < 31;

    c[4] = k2 + 2.0f * H11 + 2.0f * H22;
    c[5] = xp         ? ( 0.5f * m1 - H11) : 0.0f;
    c[3] = xm         ? (-0.5f * m1 - H11) : 0.0f;
    c[7] = yp         ? ( 0.5f * m2 - H22) : 0.0f;
    c[1] = ym         ? (-0.5f * m2 - H22) : 0.0f;
    c[8] = (xp && yp) ? (-0.5f * H12)      : 0.0f;
    c[2] = (xp && ym) ? ( 0.5f * H12)      : 0.0f;
    c[6] = (xm && yp) ? ( 0.5f * H12)      : 0.0f;
    c[0] = (xm && ym) ? (-0.5f * H12)      : 0.0f;
}

// ---------------------------------------------------------------------------
// Precompute kernel: 72 diag CTAs (9 blocks x 8 row-chunks of 128) +
// 64 offdiag CTAs (8 slices x 8 chunks). 128 threads/CTA, thread = one row.
// ---------------------------------------------------------------------------
__global__ __launch_bounds__(128)
void pre_kernel(const float* __restrict__ kappa,
                const float* __restrict__ m,
                const float* __restrict__ H) {
    __shared__ float sb[261 * 9];               // coef window
    int cb  = blockIdx.x;
    int tid = threadIdx.x;

    if (cb < 72) {
        // ---------------- diag block i ----------------
        int i = cb >> 3, chunk = cb & 7, p0 = chunk << 7;
        int t = (i == 0) ? 0 : i - 1;
        int base = max(0, p0 - 66);
        int hi   = min(NB, p0 + 128 + 66);
        int cnt  = hi - base;

        for (int idx = tid; idx < cnt; idx += 128) {
            float c[9];
            coef9(kappa, m, H, base + idx, t + 1, c);
            if (i > 0) c[4] += 1.0f;            // store B = I + A for i>=1
#pragma unroll
            for (int j = 0; j < 9; j++) sb[idx * 9 + j] = c[j];
        }
        __syncthreads();

        int p = p0 + tid;
        float aR[25], aC[25];
#pragma unroll
        for (int k = 0; k < 25; k++) { aR[k] = 0.0f; aC[k] = 0.0f; }

        if (i == 0) {
            // (A^T A)[p][p+d]: contributions a[r][8-j1]*a[r][j2], r = p+off_j1
#pragma unroll
            for (int j1 = 0; j1 < 9; j1++) {
                int dy1 = j1 / 3 - 1, dx1 = j1 - (j1 / 3) * 3 - 1;
                int r = p + dy1 * 32 + dx1;
                if (r < 0 || r >= NB) continue;
                const float* br = sb + (r - base) * 9;
                float arp = br[8 - j1];
#pragma unroll
                for (int j2 = 0; j2 < 9; j2++) {
                    int dy2 = j2 / 3 - 1, dx2 = j2 - (j2 / 3) * 3 - 1;
                    aR[(dy1 + dy2 + 2) * 5 + dx1 + dx2 + 2] += arp * br[j2];
                }
            }
        } else {
            const float* bp = sb + (p - base) * 9;
            // MM[p][p+d] = sum b[p][j1] * b[r][j2], r = p+off_j1
#pragma unroll
            for (int j1 = 0; j1 < 9; j1++) {
                int dy1 = j1 / 3 - 1, dx1 = j1 - (j1 / 3) * 3 - 1;
                int r = p + dy1 * 32 + dx1;
                if (r < 0 || r >= NB) continue;
                float bpr = bp[j1];
                const float* br = sb + (r - base) * 9;
#pragma unroll
                for (int j2 = 0; j2 < 9; j2++) {
                    int dy2 = j2 / 3 - 1, dx2 = j2 - (j2 / 3) * 3 - 1;
                    aR[(dy1 + dy2 + 2) * 5 + dx1 + dx2 + 2] += bpr * br[j2];
                }
            }
            // MM[p+d][p] = sum b[x][jx] * b[s][8-js], s = p+off_js, x = s-off_jx
#pragma unroll
            for (int js = 0; js < 9; js++) {
                int dys = js / 3 - 1, dxs = js - (js / 3) * 3 - 1;
                int s = p + dys * 32 + dxs;
                if (s < 0 || s >= NB) continue;
                float bsp = sb[(s - base) * 9 + (8 - js)];
#pragma unroll
                for (int jx = 0; jx < 9; jx++) {
                    int dyx = jx / 3 - 1, dxx = jx - (jx / 3) * 3 - 1;
                    int x = s - (dyx * 32 + dxx);
                    if (x < 0 || x >= NB) continue;
                    aC[(dys - dyx + 2) * 5 + (dxs - dxx + 2)] +=
                        sb[(x - base) * 9 + jx] * bsp;
                }
            }
        }

        float* dst = g_D + ((size_t)i * NB + p) * DW;
        for (int d = 0; d < 133; d++) dst[d] = 0.0f;
        float dadd = (i < 8) ? 1.05f : 0.05f;
#pragma unroll
        for (int ey = -2; ey <= 2; ey++)
#pragma unroll
            for (int ex = -2; ex <= 2; ex++) {
                int a = (ey + 2) * 5 + ex + 2;
                float v = (i == 0) ? aR[a] : 0.5f * (aR[a] + aC[a]);
                if (ey == 0 && ex == 0) v += dadd;
                dst[ey * 32 + ex + 66] = v;
            }
    } else {
        // ---------------- offdiag slice t ----------------
        int cb2 = cb - 72;
        int t = cb2 >> 3, chunk = cb2 & 7, p0 = chunk << 7;
        int base = max(0, p0 - 33);
        int hi   = min(NB, p0 + 128 + 33);
        int cnt  = hi - base;

        for (int idx = tid; idx < cnt; idx += 128) {
            float c[9];
            coef9(kappa, m, H, base + idx, t + 1, c);
#pragma unroll
            for (int j = 0; j < 9; j++) sb[idx * 9 + j] = c[j];
        }
        __syncthreads();

        int p = p0 + tid;
        const float* ap = sb + (p - base) * 9;
        float* dst = g_O + ((size_t)t * NB + p) * OW;
        for (int d = -33; d <= 33; d++) {
            int de = d + 33;
            float v = 0.0f;
            int q = p + d;
            if ((de & 31) <= 2 && q >= 0 && q < NB) {
                int j = (de >> 5) * 3 + (de & 31);
                float add = (j == 4) ? 2.0f : 0.0f;       // both invM get +I
                v = -0.5f * (ap[j] + sb[(q - base) * 9 + (8 - j)] + add);
            }
            dst[de] = v;
        }
    }
}

// ---------------------------------------------------------------------------
// Lean streaming fill: one CTA per output row, 9 float4 streaming stores per
// thread; in-band lanes fetch precomputed values with predicated __ldg.
// ---------------------------------------------------------------------------
__global__ __launch_bounds__(256)
void fill_kernel(float* __restrict__ out) {
    int r = blockIdx.x;                 // row 0..9215
    int i = r >> 10;                    // block row
    int p = r & (NB - 1);
    float4* rowp = (float4*)(out + (size_t)r * TN);

    const float* Dp = g_D + ((size_t)i * NB + p) * DW + 66;   // index by d
    int q0 = threadIdx.x << 2;          // column within block
    int d0 = q0 - p;

#pragma unroll
    for (int it = 0; it < 9; it++) {    // column block == it
        float4 v = make_float4(0.f, 0.f, 0.f, 0.f);
        if (it == i) {
            if (d0 + 3 >= -66 && d0 <= 66) {
                if (d0     >= -66 && d0     <= 66) v.x = __ldg(Dp + d0);
                if (d0 + 1 >= -66 && d0 + 1 <= 66) v.y = __ldg(Dp + d0 + 1);
                if (d0 + 2 >= -66 && d0 + 2 <= 66) v.z = __ldg(Dp + d0 + 2);
                if (d0 + 3 >= -66 && d0 + 3 <= 66) v.w = __ldg(Dp + d0 + 3);
            }
        } else if (it == i - 1 || it == i + 1) {
            int t = (it < i) ? it : i;  // min(i, it)
            const float* Op = g_O + ((size_t)t * NB + p) * OW + 33;
            if (d0 + 3 >= -33 && d0 <= 33) {
                if (d0     >= -33 && d0     <= 33) v.x = __ldg(Op + d0);
                if (d0 + 1 >= -33 && d0 + 1 <= 33) v.y = __ldg(Op + d0 + 1);
                if (d0 + 2 >= -33 && d0 + 2 <= 33) v.z = __ldg(Op + d0 + 2);
                if (d0 + 3 >= -33 && d0 + 3 <= 33) v.w = __ldg(Op + d0 + 3);
            }
        }
        __stcs(rowp + it * 256 + threadIdx.x, v);
    }
}

// ---------------------------------------------------------------------------
// Launcher. Inputs: kappa, m, H, tau (unused). Output: fp32 [1, 9216, 9216].
// ---------------------------------------------------------------------------
extern "C" void kernel_launch(void* const* d_in, const int* in_sizes, int n_in,
                              void* d_out, int out_size) {
    const float* kappa = (const float*)d_in[0];
    const float* m     = (const float*)d_in[1];
    const float* H     = (const float*)d_in[2];
    float* out = (float*)d_out;

    pre_kernel<<<136, 128>>>(kappa, m, H);
    fill_kernel<<<TN, 256>>>(out);
}

// round 6
// speedup vs baseline: 1.4635x; 1.2398x over previous
#include <cuda_runtime.h>
#include <cstddef>

#define NB 1024          // 32*32 nodes per time slice
#define NT 9
#define TN (NT * NB)     // 9216
#define PRE_D 36         // 9 diag blocks * 4 row-chunks of 256
#define PRE_O 32         // 8 offdiag slices * 4 chunks
#define PRE_CTAS 68

// Compact band scratch.
// g_D[i][p][slot25]: diag value at delta = ey*32+ex, slot=(ey+2)*5+(ex+2)
// g_O[t][p][j9]:     offdiag value at delta with j = (dy+1)*3+(dx+1)
__device__ float g_D[9 * NB * 25];
__device__ float g_O[8 * NB * 9];

// ---------------------------------------------------------------------------
// Per-node 9-point stencil coefficients of A at time slice ts.
// j = (dy+1)*3 + (dx+1); Dirichlet-invalid moves = exact 0.
// ---------------------------------------------------------------------------
__device__ __forceinline__ void coef9(const float* __restrict__ kappa,
                                      const float* __restrict__ m,
                                      const float* __restrict__ H,
                                      int n, int ts, float* c) {
    float kap = kappa[n * NT + ts];
    float k2  = kap * kap;
    float m1  = m[(0 * NB + n) * NT + ts];
    float m2  = m[(1 * NB + n) * NT + ts];
    float H11 = H[(0 * NB + n) * NT + ts];
    float H12 = H[(1 * NB + n) * NT + ts];
    float H22 = H[(3 * NB + n) * NT + ts];

    int ix = n & 31, iy = n >> 5;
    bool xm = ix > 0, xp = ix < 31, ym = iy > 0, yp = iy < 31;

    c[4] = k2 + 2.0f * H11 + 2.0f * H22;
    c[5] = xp         ? ( 0.5f * m1 - H11) : 0.0f;
    c[3] = xm         ? (-0.5f * m1 - H11) : 0.0f;
    c[7] = yp         ? ( 0.5f * m2 - H22) : 0.0f;
    c[1] = ym         ? (-0.5f * m2 - H22) : 0.0f;
    c[8] = (xp && yp) ? (-0.5f * H12)      : 0.0f;
    c[2] = (xp && ym) ? ( 0.5f * H12)      : 0.0f;
    c[6] = (xm && yp) ? ( 0.5f * H12)      : 0.0f;
    c[0] = (xm && ym) ? (-0.5f * H12)      : 0.0f;
}

// ---------------------------------------------------------------------------
// Kernel 1: first 68 CTAs precompute compact band values; remaining 9216
// CTAs stream zeros into the non-band column blocks of their row.
// Outputs are disjoint; kernel 2 (band blocks) depends on the pre part only.
// ---------------------------------------------------------------------------
__global__ __launch_bounds__(256, 6)
void k1(const float* __restrict__ kappa,
        const float* __restrict__ m,
        const float* __restrict__ H,
        float* __restrict__ out) {
    int cb = blockIdx.x;
    int tid = threadIdx.x;

    if (cb >= PRE_CTAS) {
        // -------- zero CTA: row r, write the 6-7 non-band column blocks ----
        int r = cb - PRE_CTAS;
        int i = r >> 10;
        float4* rowp = (float4*)(out + (size_t)r * TN);
        float4 z = make_float4(0.f, 0.f, 0.f, 0.f);
#pragma unroll
        for (int j = 0; j < 9; j++) {
            if (j < i - 1 || j > i + 1)
                __stcs(rowp + j * 256 + tid, z);
        }
        return;
    }

    __shared__ float sb[388 * 9];       // coefficient window

    if (cb < PRE_D) {
        // -------- diag block i, rows p0..p0+255 --------
        int i = cb >> 2, chunk = cb & 3, p0 = chunk << 8;
        int t = (i == 0) ? 0 : i - 1;
        int base = max(0, p0 - 66);
        int hi   = min(NB, p0 + 256 + 66);
        int cnt  = hi - base;

        for (int idx = tid; idx < cnt; idx += 256) {
            float c[9];
            coef9(kappa, m, H, base + idx, t + 1, c);
            if (i > 0) c[4] += 1.0f;    // B = I + A for i>=1
#pragma unroll
            for (int j = 0; j < 9; j++) sb[idx * 9 + j] = c[j];
        }
        __syncthreads();

        int p = p0 + tid;
        float aR[25], aC[25];
#pragma unroll
        for (int k = 0; k < 25; k++) { aR[k] = 0.0f; aC[k] = 0.0f; }

        if (i == 0) {
            // (A^T A)[p][p+d]
#pragma unroll
            for (int j1 = 0; j1 < 9; j1++) {
                int dy1 = j1 / 3 - 1, dx1 = j1 % 3 - 1;
                int r = p + dy1 * 32 + dx1;
                if (r < 0 || r >= NB) continue;
                const float* br = sb + (r - base) * 9;
                float arp = br[8 - j1];
#pragma unroll
                for (int j2 = 0; j2 < 9; j2++) {
                    int dy2 = j2 / 3 - 1, dx2 = j2 % 3 - 1;
                    aR[(dy1 + dy2 + 2) * 5 + dx1 + dx2 + 2] += arp * br[j2];
                }
            }
        } else {
            const float* bp = sb + (p - base) * 9;
            // MM[p][p+d]
#pragma unroll
            for (int j1 = 0; j1 < 9; j1++) {
                int dy1 = j1 / 3 - 1, dx1 = j1 % 3 - 1;
                int r = p + dy1 * 32 + dx1;
                if (r < 0 || r >= NB) continue;
                float bpr = bp[j1];
                const float* br = sb + (r - base) * 9;
#pragma unroll
                for (int j2 = 0; j2 < 9; j2++) {
                    int dy2 = j2 / 3 - 1, dx2 = j2 % 3 - 1;
                    aR[(dy1 + dy2 + 2) * 5 + dx1 + dx2 + 2] += bpr * br[j2];
                }
            }
            // MM[p+d][p]
#pragma unroll
            for (int js = 0; js < 9; js++) {
                int dys = js / 3 - 1, dxs = js % 3 - 1;
                int s = p + dys * 32 + dxs;
                if (s < 0 || s >= NB) continue;
                float bsp = sb[(s - base) * 9 + (8 - js)];
#pragma unroll
                for (int jx = 0; jx < 9; jx++) {
                    int dyx = jx / 3 - 1, dxx = jx % 3 - 1;
                    int x = s - (dyx * 32 + dxx);
                    if (x < 0 || x >= NB) continue;
                    aC[(dys - dyx + 2) * 5 + (dxs - dxx + 2)] +=
                        sb[(x - base) * 9 + jx] * bsp;
                }
            }
        }

        float* dst = g_D + ((size_t)i * NB + p) * 25;
        float dadd = (i < 8) ? 1.05f : 0.05f;
#pragma unroll
        for (int slot = 0; slot < 25; slot++) {
            float v = (i == 0) ? aR[slot] : 0.5f * (aR[slot] + aC[slot]);
            if (slot == 12) v += dadd;
            dst[slot] = v;
        }
    } else {
        // -------- offdiag slice t, rows p0..p0+255 --------
        int cb2 = cb - PRE_D;
        int t = cb2 >> 2, chunk = cb2 & 3, p0 = chunk << 8;
        int base = max(0, p0 - 33);
        int hi   = min(NB, p0 + 256 + 33);
        int cnt  = hi - base;

        for (int idx = tid; idx < cnt; idx += 256) {
            float c[9];
            coef9(kappa, m, H, base + idx, t + 1, c);
#pragma unroll
            for (int j = 0; j < 9; j++) sb[idx * 9 + j] = c[j];
        }
        __syncthreads();

        int p = p0 + tid;
        const float* ap = sb + (p - base) * 9;
        float* dst = g_O + ((size_t)t * NB + p) * 9;
#pragma unroll
        for (int j = 0; j < 9; j++) {
            int dy = j / 3 - 1, dx = j % 3 - 1;
            int q = p + dy * 32 + dx;
            float v = 0.0f;
            if (q >= 0 && q < NB) {
                float add = (j == 4) ? 2.0f : 0.0f;   // both invM get +I
                v = -0.5f * (ap[j] + sb[(q - base) * 9 + (8 - j)] + add);
            }
            dst[j] = v;
        }
    }
}

// ---------------------------------------------------------------------------
// Compact-scratch lookups for kernel 2.
// ---------------------------------------------------------------------------
__device__ __forceinline__ float dg(const float* __restrict__ Dp, int d) {
    if (d < -66 || d > 66) return 0.0f;
    int ey = ((d + 68) >> 5) - 2;       // d+68 in [2,134], safe shift
    int ex = d - (ey << 5);
    if (ex < -2 || ex > 2) return 0.0f;
    return Dp[(ey + 2) * 5 + ex + 2];
}

__device__ __forceinline__ float od(const float* __restrict__ Op, int d) {
    unsigned de = (unsigned)(d + 33);
    if (de > 66u) return 0.0f;
    unsigned rr = de & 31u;
    if (rr > 2u) return 0.0f;
    return Op[(de >> 5) * 3 + rr];
}

// ---------------------------------------------------------------------------
// Kernel 2: stream the 2-3 band column blocks of each row (values + the
// in-block zeros), reading compact scratch. Every band-block byte written once.
// ---------------------------------------------------------------------------
__global__ __launch_bounds__(256)
void k2(float* __restrict__ out) {
    int r = blockIdx.x;
    int i = r >> 10;
    int p = r & (NB - 1);
    float4* rowp = (float4*)(out + (size_t)r * TN);
    int q0 = threadIdx.x << 2;
    int d0 = q0 - p;

    {   // diag block
        const float* Dp = g_D + ((size_t)i * NB + p) * 25;
        float4 v = make_float4(0.f, 0.f, 0.f, 0.f);
        if (d0 + 3 >= -66 && d0 <= 66) {
            v.x = dg(Dp, d0);
            v.y = dg(Dp, d0 + 1);
            v.z = dg(Dp, d0 + 2);
            v.w = dg(Dp, d0 + 3);
        }
        __stcs(rowp + i * 256 + threadIdx.x, v);
    }
    if (i > 0) {                        // left offdiag, slice i-1
        const float* Op = g_O + ((size_t)(i - 1) * NB + p) * 9;
        float4 v = make_float4(0.f, 0.f, 0.f, 0.f);
        if (d0 + 3 >= -33 && d0 <= 33) {
            v.x = od(Op, d0);
            v.y = od(Op, d0 + 1);
            v.z = od(Op, d0 + 2);
            v.w = od(Op, d0 + 3);
        }
        __stcs(rowp + (i - 1) * 256 + threadIdx.x, v);
    }
    if (i < 8) {                        // right offdiag, slice i
        const float* Op = g_O + ((size_t)i * NB + p) * 9;
        float4 v = make_float4(0.f, 0.f, 0.f, 0.f);
        if (d0 + 3 >= -33 && d0 <= 33) {
            v.x = od(Op, d0);
            v.y = od(Op, d0 + 1);
            v.z = od(Op, d0 + 2);
            v.w = od(Op, d0 + 3);
        }
        __stcs(rowp + (i + 1) * 256 + threadIdx.x, v);
    }
}

// ---------------------------------------------------------------------------
// Launcher. Inputs: kappa, m, H, tau (unused). Output: fp32 [1, 9216, 9216].
// ---------------------------------------------------------------------------
extern "C" void kernel_launch(void* const* d_in, const int* in_sizes, int n_in,
                              void* d_out, int out_size) {
    const float* kappa = (const float*)d_in[0];
    const float* m     = (const float*)d_in[1];
    const float* H     = (const float*)d_in[2];
    float* out = (float*)d_out;

    k1<<<PRE_CTAS + TN, 256>>>(kappa, m, H, out);
    k2<<<TN, 256>>>(out);
}